// round 1
// baseline (speedup 1.0000x reference)
#include <cuda_runtime.h>
#include <math.h>

// ---------------------------------------------------------------------------
// TriParser: h = [sentinel; x]  (B=8, n=128, E=512, A=256)
//   7x proj: elu(h @ W + b)                     -> g_proj[7][1024,256]
//   per tri t in {sib, cop, gp}:
//     stage1: t1[bi, c*256+d] = u[bi,:] @ U_t   GEMM [1024,256]@[256,65536]
//     stage2: t2[bi, j, d]    = v[b] @ t1[bi]   1024x GEMM [128,256]@[256,256]
//     stage3: s[bi, j, k]     = t2[bi] @ w[b]^T 1024x GEMM [128,256]@[256,128]^T
// Output: sib | cop | gp | mask_full (f32)
// ---------------------------------------------------------------------------

#define BM 128
#define BN 128
#define BK 16

// scratch (device globals: allocation-free per harness rules)
__device__ float g_h[1024 * 512];              // 2 MB
__device__ float g_proj[7 * 1024 * 256];       // 7 MB
__device__ float g_t1[1024 * 256 * 256];       // 268 MB
__device__ float g_t2[1024 * 128 * 256];       // 134 MB

struct ProjArgs {
    const float* W[7];
    const float* bias[7];
};

// ---------------------------------------------------------------------------
// 128x128x16 SIMT fp32 tile. 256 threads, 8x8 per thread.
// NT=false: C = A[M,K] @ B[K,N] ; NT=true: C = A[M,K] @ B'[N,K]^T
// bias != nullptr -> add bias[col] and apply ELU (alpha=1).
// ---------------------------------------------------------------------------
template <bool NT>
__device__ __forceinline__ void gemm_tile(
    const float* __restrict__ A, const float* __restrict__ B,
    float* __restrict__ C, int K, int lda, int ldb, int ldc,
    const float* __restrict__ bias)
{
    __shared__ float As[BK][BM];
    __shared__ float Bs[BK][BN];

    const int tid = threadIdx.x;
    const int bm = blockIdx.y * BM;
    const int bn = blockIdx.x * BN;
    const int tx = tid & 15;   // 16 thread cols
    const int ty = tid >> 4;   // 16 thread rows

    float acc[8][8];
#pragma unroll
    for (int i = 0; i < 8; i++)
#pragma unroll
        for (int j = 0; j < 8; j++) acc[i][j] = 0.0f;

    for (int k0 = 0; k0 < K; k0 += BK) {
        // --- A tile: [BM, BK], coalesced LDG, transposed STS into As[k][m]
#pragma unroll
        for (int i = 0; i < 2; i++) {
            int v = tid + i * 256;
            int r = v >> 2;
            int c4 = (v & 3) << 2;
            float4 a = *(const float4*)(A + (size_t)(bm + r) * lda + k0 + c4);
            As[c4 + 0][r] = a.x;
            As[c4 + 1][r] = a.y;
            As[c4 + 2][r] = a.z;
            As[c4 + 3][r] = a.w;
        }
        // --- B tile
        if (NT) {
            // B'[N,K] row-major: same pattern as A, transposed into Bs[k][n]
#pragma unroll
            for (int i = 0; i < 2; i++) {
                int v = tid + i * 256;
                int r = v >> 2;
                int c4 = (v & 3) << 2;
                float4 b = *(const float4*)(B + (size_t)(bn + r) * ldb + k0 + c4);
                Bs[c4 + 0][r] = b.x;
                Bs[c4 + 1][r] = b.y;
                Bs[c4 + 2][r] = b.z;
                Bs[c4 + 3][r] = b.w;
            }
        } else {
            // B[K,N] row-major: coalesced, direct float4 STS (conflict-free)
#pragma unroll
            for (int i = 0; i < 2; i++) {
                int v = tid + i * 256;
                int r = v >> 5;
                int c4 = (v & 31) << 2;
                float4 b = *(const float4*)(B + (size_t)(k0 + r) * ldb + bn + c4);
                *(float4*)&Bs[r][c4] = b;
            }
        }
        __syncthreads();

#pragma unroll
        for (int kk = 0; kk < BK; kk++) {
            float ar[8], br[8];
            *(float4*)&ar[0] = *(const float4*)&As[kk][ty * 8];
            *(float4*)&ar[4] = *(const float4*)&As[kk][ty * 8 + 4];
            *(float4*)&br[0] = *(const float4*)&Bs[kk][tx * 8];
            *(float4*)&br[4] = *(const float4*)&Bs[kk][tx * 8 + 4];
#pragma unroll
            for (int i = 0; i < 8; i++)
#pragma unroll
                for (int j = 0; j < 8; j++)
                    acc[i][j] = fmaf(ar[i], br[j], acc[i][j]);
        }
        __syncthreads();
    }

    // --- epilogue
#pragma unroll
    for (int i = 0; i < 8; i++) {
        int row = bm + ty * 8 + i;
#pragma unroll
        for (int j = 0; j < 8; j += 4) {
            int col = bn + tx * 8 + j;
            float v0 = acc[i][j + 0], v1 = acc[i][j + 1];
            float v2 = acc[i][j + 2], v3 = acc[i][j + 3];
            if (bias) {
                v0 += bias[col + 0];
                v1 += bias[col + 1];
                v2 += bias[col + 2];
                v3 += bias[col + 3];
                v0 = v0 > 0.f ? v0 : expm1f(v0);
                v1 = v1 > 0.f ? v1 : expm1f(v1);
                v2 = v2 > 0.f ? v2 : expm1f(v2);
                v3 = v3 > 0.f ? v3 : expm1f(v3);
            }
            *(float4*)(C + (size_t)row * ldc + col) = make_float4(v0, v1, v2, v3);
        }
    }
}

template <bool NT>
__global__ __launch_bounds__(256, 2)
void batched_sgemm(const float* __restrict__ A, const float* __restrict__ B,
                   float* __restrict__ C, int K, int lda, int ldb, int ldc,
                   unsigned long long aStride, int aShift,
                   unsigned long long bStride, int bShift,
                   unsigned long long cStride)
{
    size_t z = blockIdx.z;
    gemm_tile<NT>(A + (z >> aShift) * (size_t)aStride,
                  B + (z >> bShift) * (size_t)bStride,
                  C + z * (size_t)cStride,
                  K, lda, ldb, ldc, nullptr);
}

__global__ __launch_bounds__(256, 2)
void proj_gemm(ProjArgs pa, const float* __restrict__ h, float* __restrict__ outp)
{
    int z = blockIdx.z;  // branch 0..6
    gemm_tile<false>(h, pa.W[z], outp + (size_t)z * (1024 * 256),
                     512, 512, 256, 256, pa.bias[z]);
}

__global__ void build_h(const float* __restrict__ x, const float* __restrict__ sent,
                        float* __restrict__ h)
{
    int idx = blockIdx.x * blockDim.x + threadIdx.x;  // exactly 1024*512 threads
    int row = idx >> 9;
    int e = idx & 511;
    int t = row & 127;
    int b = row >> 7;
    h[idx] = (t == 0) ? sent[e] : x[((size_t)(b * 127 + t - 1)) * 512 + e];
}

__global__ void write_mask(const int* __restrict__ mask, float* __restrict__ outm)
{
    int i = blockIdx.x * blockDim.x + threadIdx.x;
    if (i < 1024) {
        int b = i >> 7, t = i & 127;
        outm[i] = (t == 0) ? 1.0f : (float)mask[b * 127 + t - 1];
    }
}

extern "C" void kernel_launch(void* const* d_in, const int* in_sizes, int n_in,
                              void* d_out, int out_size)
{
    (void)in_sizes; (void)n_in; (void)out_size;

    const float* x    = (const float*)d_in[0];
    // d_in[1] = pos_tags (unused by reference)
    const int*   mask = (const int*)d_in[2];
    const float* U[3] = { (const float*)d_in[17],   // U_sib
                          (const float*)d_in[18],   // U_cop
                          (const float*)d_in[19] }; // U_gp
    const float* sent = (const float*)d_in[20];
    float* out = (float*)d_out;

    float *h, *proj, *t1, *t2;
    cudaGetSymbolAddress((void**)&h,    g_h);
    cudaGetSymbolAddress((void**)&proj, g_proj);
    cudaGetSymbolAddress((void**)&t1,   g_t1);
    cudaGetSymbolAddress((void**)&t2,   g_t2);

    build_h<<<2048, 256>>>(x, sent, h);

    const size_t SCORES = (size_t)3 * 8 * 128 * 128 * 128;  // 50331648
    write_mask<<<4, 256>>>(mask, out + SCORES);

    ProjArgs pa;
    for (int i = 0; i < 7; i++) {
        pa.W[i]    = (const float*)d_in[3 + 2 * i];
        pa.bias[i] = (const float*)d_in[4 + 2 * i];
    }
    // branches order: 0 sib_head, 1 sib_dep, 2 cop_head, 3 cop_dep,
    //                 4 gp_head, 5 gp_dep, 6 gp_head_dep
    proj_gemm<<<dim3(2, 8, 7), 256>>>(pa, h, proj);

    const size_t PS = 1024 * 256;          // proj branch stride
    const int ui[3] = {0, 2, 4};           // u operand branch
    const int vi[3] = {1, 3, 6};           // v operand branch
    const int wi[3] = {1, 2, 5};           // w operand branch

    for (int t = 0; t < 3; t++) {
        // stage1: t1[1024, 65536] = u[1024,256] @ U[256,65536]
        batched_sgemm<false><<<dim3(512, 8, 1), 256>>>(
            proj + ui[t] * PS, U[t], t1,
            256, 256, 65536, 65536,
            0ULL, 0, 0ULL, 0, 0ULL);

        // stage2: per bi: t2[bi] = v[b] @ t1[bi]   ([128,256]@[256,256])
        batched_sgemm<false><<<dim3(2, 1, 1024), 256>>>(
            proj + vi[t] * PS, t1, t2,
            256, 256, 256, 256,
            32768ULL, 7,      // v: b = bi>>7, stride 128*256
            65536ULL, 0,      // t1: stride per bi
            32768ULL);        // t2: stride per bi

        // stage3: per bi: s[bi] = t2[bi] @ w[b]^T  ([128,256]@[256,128])
        batched_sgemm<true><<<dim3(1, 1, 1024), 256>>>(
            t2, proj + wi[t] * PS,
            out + (size_t)t * 16777216,
            256, 256, 256, 128,
            32768ULL, 0,      // t2 per bi
            32768ULL, 7,      // w: per batch b
            16384ULL);        // out per bi
    }
}

// round 3
// speedup vs baseline: 2.3954x; 2.3954x over previous
#include <cuda_runtime.h>
#include <cuda_bf16.h>
#include <cstdint>
#include <math.h>

typedef __nv_bfloat16 bf16;

// ===========================================================================
// TriParser via mma.sync (HMMA bf16, f32 acc) — compute_103-safe tensor path.
//   h = [sentinel; x]  (B=8, n=128, E=512, A=256), tokens bi in [0,1024)
//   proj: elu(h@W+b) -> bf16 hi|lo rows [1024, 512]  (7 branches)
//   Up:   U[a,c,d] -> rows r=d*256+c, cols a hi|lo   [65536, 512]
//   stage1: t1[bi][d][c] = sum_a u[bi,a] U[a,c,d]     D = u @ Up^T
//   stage2: t2[bi][j][d] = sum_c v[b,j,c] t1[bi][d,c] D = v @ t1^T
//   stage3: s[bi][j][k]  = sum_d t2[bi,j,d] w[b,k,d]  D = t2 @ w^T  (f32 out)
// Each value x carried as bf16 pair (hi, lo); D = Ah@Bh + Ah@Bl + Al@Bh.
// ===========================================================================

__device__ float g_h[1024 * 512];                      // 2 MB
__device__ bf16  g_projb[7 * 1024 * 512];              // 7 MB
__device__ bf16  g_Up[3ull * 65536 * 512];             // 192 MB
__device__ bf16  g_t1[1024ull * 256 * 512];            // 268 MB
__device__ bf16  g_t2[1024ull * 128 * 512];            // 134 MB

__device__ __forceinline__ uint32_t smem_u32(const void* p) {
    uint32_t a;
    asm("{ .reg .u64 t; cvta.to.shared.u64 t, %1; cvt.u32.u64 %0, t; }"
        : "=r"(a) : "l"(p));
    return a;
}

#define SW128(o) ((o) ^ (((o) >> 3) & 0x70))

__device__ __forceinline__ void ldm_x4(uint32_t* r, uint32_t addr) {
    asm volatile("ldmatrix.sync.aligned.m8n8.x4.shared.b16 {%0,%1,%2,%3}, [%4];"
                 : "=r"(r[0]), "=r"(r[1]), "=r"(r[2]), "=r"(r[3]) : "r"(addr));
}

__device__ __forceinline__ void mma16816(float* c, const uint32_t* a, const uint32_t* b) {
    asm volatile(
        "mma.sync.aligned.m16n8k16.row.col.f32.bf16.bf16.f32 "
        "{%0,%1,%2,%3}, {%4,%5,%6,%7}, {%8,%9}, {%0,%1,%2,%3};"
        : "+f"(c[0]), "+f"(c[1]), "+f"(c[2]), "+f"(c[3])
        : "r"(a[0]), "r"(a[1]), "r"(a[2]), "r"(a[3]), "r"(b[0]), "r"(b[1]));
}

__device__ __forceinline__ void cpa16(uint32_t dst, const void* src) {
    asm volatile("cp.async.cg.shared.global [%0], [%1], 16;" :: "r"(dst), "l"(src) : "memory");
}
#define CP_COMMIT() asm volatile("cp.async.commit_group;" ::: "memory")

// ===========================================================================
// MMA stage: grid (x = M-tiles, y = N-tiles, z = batch), 128 threads.
// A, B: [rows, 512] bf16 (hi cols 0:256, lo 256:512). CTA tile 128x128, K=256.
// EPI=0: bf16 hi|lo output rows (stride cRowStride); EPI=1: f32 rows (stride 128).
// S1MAP=1: stage1 column mapping (N-tile y covers r=d*256+c).
// ===========================================================================
template <int EPI, int S1MAP>
__global__ __launch_bounds__(128)
void mma_stage(const bf16* __restrict__ A, const bf16* __restrict__ B,
               void* __restrict__ Cv,
               unsigned long long aBatch, int aShift,
               unsigned long long bBatch, int bShift,
               unsigned long long cBatch, unsigned long long cRowStride)
{
    extern __shared__ char dsm[];
    const uint32_t sraw = smem_u32(dsm);
    const uint32_t sb = (sraw + 1023u) & ~1023u;   // 1KB-align for SW128

    const int tid = threadIdx.x;
    const int lane = tid & 31;
    const int warp = tid >> 5;
    const int wm = warp >> 1;       // 2x2 warps, 64x64 warp tile
    const int wn = warp & 1;
    const size_t z = blockIdx.z;

    const bf16* Ab = A + (z >> aShift) * (size_t)aBatch + (size_t)blockIdx.x * 65536;
    const bf16* Bb = B + (z >> bShift) * (size_t)bBatch + (size_t)blockIdx.y * 65536;

    // buffer: Ah(16K) Al(16K) Bh(16K) Bl(16K) = 64KB, x2
    auto issue = [&](int c) {
        const uint32_t base = sb + (c & 1) * 65536;
        const bf16* srcs[4] = { Ab + c * 64, Ab + 256 + c * 64,
                                Bb + c * 64, Bb + 256 + c * 64 };
#pragma unroll
        for (int t = 0; t < 4; t++) {
#pragma unroll
            for (int i = 0; i < 8; i++) {
                int idx = tid + i * 128;
                int row = idx >> 3, seg = idx & 7;
                cpa16(base + t * 16384 + SW128(row * 128 + seg * 16),
                      srcs[t] + (size_t)row * 512 + seg * 8);
            }
        }
        CP_COMMIT();
    };

    float acc[4][8][4];
#pragma unroll
    for (int i = 0; i < 4; i++)
#pragma unroll
        for (int j = 0; j < 8; j++)
#pragma unroll
            for (int k = 0; k < 4; k++) acc[i][j][k] = 0.0f;

    issue(0);
    issue(1);

    // ldmatrix per-lane byte offsets (pre-swizzle)
    const int aLB = ((lane & 15) * 128) + ((lane >> 4) * 16);
    const int bLB = (((lane & 7) + ((lane >> 4) << 3)) * 128) + (((lane >> 3) & 1) * 16);

#pragma unroll
    for (int c = 0; c < 4; c++) {
        if (c < 3) asm volatile("cp.async.wait_group 1;" ::: "memory");
        else       asm volatile("cp.async.wait_group 0;" ::: "memory");
        __syncthreads();
        const uint32_t base = sb + (c & 1) * 65536;

#pragma unroll
        for (int kk = 0; kk < 4; kk++) {
            uint32_t ah[4][4], al[4][4], bh[4][4], bl[4][4];
#pragma unroll
            for (int mi = 0; mi < 4; mi++) {
                int off = aLB + (wm * 64 + mi * 16) * 128 + kk * 32;
                ldm_x4(ah[mi], base + SW128(off));
                ldm_x4(al[mi], base + 16384 + SW128(off));
            }
#pragma unroll
            for (int nj = 0; nj < 4; nj++) {
                int off = bLB + (wn * 64 + nj * 16) * 128 + kk * 32;
                ldm_x4(bh[nj], base + 32768 + SW128(off));
                ldm_x4(bl[nj], base + 49152 + SW128(off));
            }
#pragma unroll
            for (int mi = 0; mi < 4; mi++)
#pragma unroll
                for (int nj = 0; nj < 4; nj++) {
                    mma16816(acc[mi][nj * 2],     ah[mi], &bh[nj][0]);
                    mma16816(acc[mi][nj * 2 + 1], ah[mi], &bh[nj][2]);
                    mma16816(acc[mi][nj * 2],     ah[mi], &bl[nj][0]);
                    mma16816(acc[mi][nj * 2 + 1], ah[mi], &bl[nj][2]);
                    mma16816(acc[mi][nj * 2],     al[mi], &bh[nj][0]);
                    mma16816(acc[mi][nj * 2 + 1], al[mi], &bh[nj][2]);
                }
        }
        if (c < 2) { __syncthreads(); issue(c + 2); }
    }

    // ---------------- epilogue (direct STG from fragments) ------------------
    const int gRow = lane >> 2;        // 0..7
    const int cPair = (lane & 3) * 2;  // 0,2,4,6

    if (EPI == 0) {
        bf16* Cb = (bf16*)Cv + z * cBatch;
        const size_t colBase = S1MAP
            ? ((size_t)(blockIdx.y >> 1) * 512 + (size_t)(blockIdx.y & 1) * 128)
            : (size_t)blockIdx.y * 128;
#pragma unroll
        for (int mi = 0; mi < 4; mi++) {
            int rbase = blockIdx.x * 128 + wm * 64 + mi * 16 + gRow;
#pragma unroll
            for (int f = 0; f < 8; f++) {
                int nloc = wn * 64 + f * 8 + cPair;
#pragma unroll
                for (int hh = 0; hh < 2; hh++) {
                    float v0 = acc[mi][f][hh * 2 + 0];
                    float v1 = acc[mi][f][hh * 2 + 1];
                    size_t row = (size_t)(rbase + hh * 8);
                    bf16 h0 = __float2bfloat16(v0);
                    bf16 l0 = __float2bfloat16(v0 - __bfloat162float(h0));
                    bf16 h1 = __float2bfloat16(v1);
                    bf16 l1 = __float2bfloat16(v1 - __bfloat162float(h1));
                    __nv_bfloat162 ph; ph.x = h0; ph.y = h1;
                    __nv_bfloat162 pl; pl.x = l0; pl.y = l1;
                    *(__nv_bfloat162*)(Cb + row * cRowStride + colBase + nloc) = ph;
                    *(__nv_bfloat162*)(Cb + row * cRowStride + colBase + 256 + nloc) = pl;
                }
            }
        }
    } else {
        float* Cb = (float*)Cv + z * cBatch;
#pragma unroll
        for (int mi = 0; mi < 4; mi++) {
            int rbase = blockIdx.x * 128 + wm * 64 + mi * 16 + gRow;
#pragma unroll
            for (int f = 0; f < 8; f++) {
                int col = blockIdx.y * 128 + wn * 64 + f * 8 + cPair;
#pragma unroll
                for (int hh = 0; hh < 2; hh++) {
                    size_t row = (size_t)(rbase + hh * 8);
                    *(float2*)(Cb + row * 128 + col) =
                        make_float2(acc[mi][f][hh * 2 + 0], acc[mi][f][hh * 2 + 1]);
                }
            }
        }
    }
}

// ===========================================================================
// Projection GEMM (SIMT fp32): elu(h @ W + b) -> bf16 hi|lo rows [1024,512]
// ===========================================================================
struct ProjArgs {
    const float* W[7];
    const float* bias[7];
};

__global__ __launch_bounds__(256, 2)
void proj_gemm(ProjArgs pa, const float* __restrict__ h, bf16* __restrict__ outp)
{
    __shared__ float As[16][128];
    __shared__ float Bs[16][128];

    const int br = blockIdx.z;
    const float* A = h;
    const float* B = pa.W[br];
    const float* bias = pa.bias[br];

    const int tid = threadIdx.x;
    const int bm = blockIdx.y * 128;
    const int bn = blockIdx.x * 128;
    const int tx = tid & 15;
    const int ty = tid >> 4;

    float acc[8][8];
#pragma unroll
    for (int i = 0; i < 8; i++)
#pragma unroll
        for (int j = 0; j < 8; j++) acc[i][j] = 0.0f;

    for (int k0 = 0; k0 < 512; k0 += 16) {
#pragma unroll
        for (int i = 0; i < 2; i++) {
            int v = tid + i * 256;
            int r = v >> 2;
            int c4 = (v & 3) << 2;
            float4 a = *(const float4*)(A + (size_t)(bm + r) * 512 + k0 + c4);
            As[c4 + 0][r] = a.x; As[c4 + 1][r] = a.y;
            As[c4 + 2][r] = a.z; As[c4 + 3][r] = a.w;
        }
#pragma unroll
        for (int i = 0; i < 2; i++) {
            int v = tid + i * 256;
            int r = v >> 5;
            int c4 = (v & 31) << 2;
            float4 b = *(const float4*)(B + (size_t)(k0 + r) * 256 + bn + c4);
            *(float4*)&Bs[r][c4] = b;
        }
        __syncthreads();
#pragma unroll
        for (int kk = 0; kk < 16; kk++) {
            float ar[8], brg[8];
            *(float4*)&ar[0] = *(const float4*)&As[kk][ty * 8];
            *(float4*)&ar[4] = *(const float4*)&As[kk][ty * 8 + 4];
            *(float4*)&brg[0] = *(const float4*)&Bs[kk][tx * 8];
            *(float4*)&brg[4] = *(const float4*)&Bs[kk][tx * 8 + 4];
#pragma unroll
            for (int i = 0; i < 8; i++)
#pragma unroll
                for (int j = 0; j < 8; j++)
                    acc[i][j] = fmaf(ar[i], brg[j], acc[i][j]);
        }
        __syncthreads();
    }

    bf16* Co = outp + (size_t)br * (1024 * 512);
#pragma unroll
    for (int i = 0; i < 8; i++) {
        int r = bm + ty * 8 + i;
#pragma unroll
        for (int j = 0; j < 8; j++) {
            int col = bn + tx * 8 + j;
            float v = acc[i][j] + bias[col];
            v = v > 0.f ? v : expm1f(v);
            bf16 hb = __float2bfloat16(v);
            bf16 lb = __float2bfloat16(v - __bfloat162float(hb));
            Co[(size_t)r * 512 + col] = hb;
            Co[(size_t)r * 512 + 256 + col] = lb;
        }
    }
}

// ===========================================================================
// U permute+split: U[a,c,d] f32 -> Up[(d*256+c)][a] hi, [(d*256+c)][256+a] lo
// ===========================================================================
__global__ void uconv(const float* __restrict__ U, bf16* __restrict__ Up)
{
    __shared__ float t[32][33];
    const int c = blockIdx.z;
    const int d0 = blockIdx.x * 32;
    const int a0 = blockIdx.y * 32;
    const int tx = threadIdx.x;
    const int ty = threadIdx.y;

#pragma unroll
    for (int i = 0; i < 32; i += 8)
        t[ty + i][tx] = U[(size_t)(a0 + ty + i) * 65536 + c * 256 + d0 + tx];
    __syncthreads();
#pragma unroll
    for (int i = 0; i < 32; i += 8) {
        int dl = ty + i;
        float v = t[tx][dl];
        bf16 hb = __float2bfloat16(v);
        bf16 lb = __float2bfloat16(v - __bfloat162float(hb));
        size_t rowbase = ((size_t)(d0 + dl) * 256 + c) * 512;
        Up[rowbase + a0 + tx] = hb;
        Up[rowbase + 256 + a0 + tx] = lb;
    }
}

__global__ void build_h(const float* __restrict__ x, const float* __restrict__ sent,
                        float* __restrict__ h)
{
    int idx = blockIdx.x * blockDim.x + threadIdx.x;
    int rowi = idx >> 9;
    int e = idx & 511;
    int t = rowi & 127;
    int b = rowi >> 7;
    h[idx] = (t == 0) ? sent[e] : x[((size_t)(b * 127 + t - 1)) * 512 + e];
}

__global__ void write_mask(const int* __restrict__ mask, float* __restrict__ outm)
{
    int i = blockIdx.x * blockDim.x + threadIdx.x;
    if (i < 1024) {
        int b = i >> 7, t = i & 127;
        outm[i] = (t == 0) ? 1.0f : (float)mask[b * 127 + t - 1];
    }
}

// ===========================================================================
extern "C" void kernel_launch(void* const* d_in, const int* in_sizes, int n_in,
                              void* d_out, int out_size)
{
    (void)in_sizes; (void)n_in; (void)out_size;

    const float* x    = (const float*)d_in[0];
    const int*   mask = (const int*)d_in[2];
    const float* U[3] = { (const float*)d_in[17], (const float*)d_in[18], (const float*)d_in[19] };
    const float* sent = (const float*)d_in[20];
    float* out = (float*)d_out;

    float* h;
    bf16 *projb, *Up, *t1, *t2;
    cudaGetSymbolAddress((void**)&h,     g_h);
    cudaGetSymbolAddress((void**)&projb, g_projb);
    cudaGetSymbolAddress((void**)&Up,    g_Up);
    cudaGetSymbolAddress((void**)&t1,    g_t1);
    cudaGetSymbolAddress((void**)&t2,    g_t2);

    const int SMEM = 2 * 65536 + 1024;
    cudaFuncSetAttribute(mma_stage<0, 1>, cudaFuncAttributeMaxDynamicSharedMemorySize, SMEM);
    cudaFuncSetAttribute(mma_stage<0, 0>, cudaFuncAttributeMaxDynamicSharedMemorySize, SMEM);
    cudaFuncSetAttribute(mma_stage<1, 0>, cudaFuncAttributeMaxDynamicSharedMemorySize, SMEM);

    build_h<<<2048, 256>>>(x, sent, h);

    const size_t SCORES = (size_t)3 * 16777216;
    write_mask<<<4, 256>>>(mask, out + SCORES);

    ProjArgs pa;
    for (int i = 0; i < 7; i++) {
        pa.W[i]    = (const float*)d_in[3 + 2 * i];
        pa.bias[i] = (const float*)d_in[4 + 2 * i];
    }
    proj_gemm<<<dim3(2, 8, 7), 256>>>(pa, h, projb);

    for (int t = 0; t < 3; t++)
        uconv<<<dim3(8, 8, 256), dim3(32, 8)>>>(U[t], Up + (size_t)t * 65536 * 512);

    const size_t PB = 1024 * 512;
    const int ui[3] = {0, 2, 4};
    const int vi[3] = {1, 3, 6};
    const int wi[3] = {1, 2, 5};

    for (int t = 0; t < 3; t++) {
        // stage1: D[1024, 65536] = u @ Up^T ; grid x fastest -> 8 CTAs share B tile
        mma_stage<0, 1><<<dim3(8, 512, 1), 128, SMEM>>>(
            projb + ui[t] * PB, Up + (size_t)t * 65536 * 512, t1,
            0ULL, 0, 0ULL, 0, 0ULL, 131072ULL);

        // stage2: per bi: t2[bi][j][d] = v[b] @ t1[bi]^T (N=256 -> y=2)
        mma_stage<0, 0><<<dim3(1, 2, 1024), 128, SMEM>>>(
            projb + vi[t] * PB, t1, t2,
            65536ULL, 7, 131072ULL, 0, 65536ULL, 512ULL);

        // stage3: per bi: s[bi][j][k] = t2[bi] @ w[b]^T (f32 out)
        mma_stage<1, 0><<<dim3(1, 1, 1024), 128, SMEM>>>(
            t2, projb + wi[t] * PB, out + (size_t)t * 16777216,
            65536ULL, 0, 65536ULL, 7, 16384ULL, 128ULL);
    }
}

// round 4
// speedup vs baseline: 2.4051x; 1.0040x over previous
#include <cuda_runtime.h>
#include <cuda_bf16.h>
#include <cstdint>
#include <math.h>

typedef __nv_bfloat16 bf16;

// ===========================================================================
// TriParser via mma.sync (HMMA bf16, f32 acc), split-bf16 (hi/lo) fp32 emu.
//   proj: elu(h@W+b) -> bf16 hi|lo rows [1024, 512]   (7 branches)
//   Up:   U[a,c,d] -> rows r=d*256+c, cols a hi|lo    [65536, 512]
//   stage1: t1[bi][d][c] = u @ Up^T          (kernel stage1_mma)
//   stage2+3 fused per token bi:
//       t2[j][d] = v[b] @ t1[bi]^T  -> smem (hi|lo packed SW128 tiles)
//       s[j][k]  = t2 @ w[b]^T      -> f32 out
// D = Ah@Bh + Ah@Bl + Al@Bh   (three HMMA products per value)
// ===========================================================================

__device__ float g_h[1024 * 512];                      // 2 MB
__device__ bf16  g_projb[7 * 1024 * 512];              // 7 MB
__device__ bf16  g_Up[3ull * 65536 * 512];             // 192 MB
__device__ bf16  g_t1[1024ull * 256 * 512];            // 268 MB

__device__ __forceinline__ uint32_t smem_u32(const void* p) {
    uint32_t a;
    asm("{ .reg .u64 t; cvta.to.shared.u64 t, %1; cvt.u32.u64 %0, t; }"
        : "=r"(a) : "l"(p));
    return a;
}

#define SW128(o) ((o) ^ (((o) >> 3) & 0x70))

__device__ __forceinline__ void ldm_x4(uint32_t* r, uint32_t addr) {
    asm volatile("ldmatrix.sync.aligned.m8n8.x4.shared.b16 {%0,%1,%2,%3}, [%4];"
                 : "=r"(r[0]), "=r"(r[1]), "=r"(r[2]), "=r"(r[3]) : "r"(addr));
}

__device__ __forceinline__ void mma16816(float* c, const uint32_t* a, const uint32_t* b) {
    asm volatile(
        "mma.sync.aligned.m16n8k16.row.col.f32.bf16.bf16.f32 "
        "{%0,%1,%2,%3}, {%4,%5,%6,%7}, {%8,%9}, {%0,%1,%2,%3};"
        : "+f"(c[0]), "+f"(c[1]), "+f"(c[2]), "+f"(c[3])
        : "r"(a[0]), "r"(a[1]), "r"(a[2]), "r"(a[3]), "r"(b[0]), "r"(b[1]));
}

__device__ __forceinline__ void cpa16(uint32_t dst, const void* src) {
    asm volatile("cp.async.cg.shared.global [%0], [%1], 16;" :: "r"(dst), "l"(src) : "memory");
}
#define CP_COMMIT() asm volatile("cp.async.commit_group;" ::: "memory")
#define CP_WAIT1()  asm volatile("cp.async.wait_group 1;" ::: "memory")
#define CP_WAIT0()  asm volatile("cp.async.wait_group 0;" ::: "memory")

// ---------------------------------------------------------------------------
// Packed tile loader: source rows [row, 512] bf16 (hi 0:256 | lo 256:512).
// Chunk c covers K cols [c*32, c*32+32). Tile = 128 rows x 128B:
//   bytes [0,64)  = hi chunk, bytes [64,128) = lo chunk, SW128-swizzled.
// 256 threads, 4 x 16B per thread, 16KB total.
// ---------------------------------------------------------------------------
__device__ __forceinline__ void load_packed(const bf16* __restrict__ g, int c,
                                            uint32_t dst, int tid) {
#pragma unroll
    for (int i = 0; i < 4; i++) {
        int idx = tid + i * 256;
        int row = idx >> 3, seg = idx & 7;
        int col = (seg < 4) ? c * 32 + seg * 8 : 256 + c * 32 + (seg - 4) * 8;
        cpa16(dst + SW128(row * 128 + seg * 16), g + (size_t)row * 512 + col);
    }
}

// ---------------------------------------------------------------------------
// One K-chunk (32) of the 128x128 3-product MMA. Warp tile 32x64 (wm 0-3, wn 0-1).
// aBase/bBase: packed tiles (hi at +0, lo at +64 within each 128B row).
// ---------------------------------------------------------------------------
__device__ __forceinline__ void mma_chunk(uint32_t aBase, uint32_t bBase,
                                          float (&acc)[2][8][4],
                                          int aLB, int bLB, int wm, int wn) {
#pragma unroll
    for (int kk = 0; kk < 2; kk++) {
        uint32_t ah[2][4], al[2][4], bh[4][4], bl[4][4];
#pragma unroll
        for (int mi = 0; mi < 2; mi++) {
            int off = aLB + (wm * 32 + mi * 16) * 128 + kk * 32;
            ldm_x4(ah[mi], aBase + SW128(off));
            ldm_x4(al[mi], aBase + SW128(off + 64));
        }
#pragma unroll
        for (int nj = 0; nj < 4; nj++) {
            int off = bLB + (wn * 64 + nj * 16) * 128 + kk * 32;
            ldm_x4(bh[nj], bBase + SW128(off));
            ldm_x4(bl[nj], bBase + SW128(off + 64));
        }
#pragma unroll
        for (int mi = 0; mi < 2; mi++)
#pragma unroll
            for (int nj = 0; nj < 4; nj++) {
                mma16816(acc[mi][nj * 2],     ah[mi], &bh[nj][0]);
                mma16816(acc[mi][nj * 2 + 1], ah[mi], &bh[nj][2]);
                mma16816(acc[mi][nj * 2],     ah[mi], &bl[nj][0]);
                mma16816(acc[mi][nj * 2 + 1], ah[mi], &bl[nj][2]);
                mma16816(acc[mi][nj * 2],     al[mi], &bh[nj][0]);
                mma16816(acc[mi][nj * 2 + 1], al[mi], &bh[nj][2]);
            }
    }
}

#define ZERO_ACC(acc) \
    { _Pragma("unroll") for (int i = 0; i < 2; i++) \
      _Pragma("unroll") for (int j = 0; j < 8; j++) \
      _Pragma("unroll") for (int k = 0; k < 4; k++) acc[i][j][k] = 0.0f; }

// ===========================================================================
// Stage1: t1 = u @ Up^T.  grid (8 M-tiles, 512 N-tiles), 256 threads.
// ===========================================================================
__global__ __launch_bounds__(256, 1)
void stage1_mma(const bf16* __restrict__ A, const bf16* __restrict__ B,
                bf16* __restrict__ C)
{
    extern __shared__ char dsm[];
    const uint32_t sraw = smem_u32(dsm);
    const uint32_t sb = (sraw + 1023u) & ~1023u;

    const int tid = threadIdx.x;
    const int lane = tid & 31;
    const int warp = tid >> 5;
    const int wm = warp >> 1, wn = warp & 1;
    const int aLB = ((lane & 15) * 128) + ((lane >> 4) * 16);
    const int bLB = (((lane & 7) + ((lane >> 4) << 3)) * 128) + (((lane >> 3) & 1) * 16);

    const bf16* Ab = A + (size_t)blockIdx.x * 65536;
    const bf16* Bb = B + (size_t)blockIdx.y * 65536;

    float acc[2][8][4];
    ZERO_ACC(acc);

    auto issue = [&](int c) {
        uint32_t buf = sb + (c & 1) * 32768;
        load_packed(Ab, c, buf, tid);
        load_packed(Bb, c, buf + 16384, tid);
        CP_COMMIT();
    };
    issue(0); issue(1);

#pragma unroll
    for (int c = 0; c < 8; c++) {
        if (c < 7) CP_WAIT1(); else CP_WAIT0();
        __syncthreads();
        uint32_t buf = sb + (c & 1) * 32768;
        mma_chunk(buf, buf + 16384, acc, aLB, bLB, wm, wn);
        if (c < 6) { __syncthreads(); issue(c + 2); }
    }

    // epilogue: bf16 hi|lo into t1[bi][d][hi 256 | lo 256]
    const int gRow = lane >> 2;
    const int cPair = (lane & 3) * 2;
    const size_t colBase = (size_t)(blockIdx.y >> 1) * 512 + (size_t)(blockIdx.y & 1) * 128;
#pragma unroll
    for (int mi = 0; mi < 2; mi++) {
        int rbase = blockIdx.x * 128 + wm * 32 + mi * 16 + gRow;
#pragma unroll
        for (int f = 0; f < 8; f++) {
            int nloc = wn * 64 + f * 8 + cPair;
#pragma unroll
            for (int hh = 0; hh < 2; hh++) {
                float v0 = acc[mi][f][hh * 2 + 0];
                float v1 = acc[mi][f][hh * 2 + 1];
                size_t row = (size_t)(rbase + hh * 8);
                bf16 h0 = __float2bfloat16(v0);
                bf16 l0 = __float2bfloat16(v0 - __bfloat162float(h0));
                bf16 h1 = __float2bfloat16(v1);
                bf16 l1 = __float2bfloat16(v1 - __bfloat162float(h1));
                __nv_bfloat162 ph; ph.x = h0; ph.y = h1;
                __nv_bfloat162 pl; pl.x = l0; pl.y = l1;
                *(__nv_bfloat162*)(C + row * 131072 + colBase + nloc) = ph;
                *(__nv_bfloat162*)(C + row * 131072 + colBase + 256 + nloc) = pl;
            }
        }
    }
}

// ===========================================================================
// Fused stage2+3 per token bi. grid 1024, 256 threads.
//   phase A: t2[j][d] = v[b] @ t1[bi]^T, two 128x128 halves -> smem packed tiles
//   phase B: s[j][k]  = t2 @ w[b]^T from smem -> f32 out
// smem: D tiles 8 x 16KB = 128KB, pipe 64KB.
// ===========================================================================
__global__ __launch_bounds__(256, 1)
void fused_stage23(const bf16* __restrict__ V, const bf16* __restrict__ T1,
                   const bf16* __restrict__ W, float* __restrict__ OUT)
{
    extern __shared__ char dsm[];
    const uint32_t sraw = smem_u32(dsm);
    const uint32_t sb = (sraw + 1023u) & ~1023u;
    char* sbp = dsm + (sb - sraw);
    const uint32_t sbD = sb;            // 131072 bytes: 8 packed D tiles
    const uint32_t sbP = sb + 131072;   // pipeline region

    const int tid = threadIdx.x;
    const int lane = tid & 31;
    const int warp = tid >> 5;
    const int wm = warp >> 1, wn = warp & 1;
    const int aLB = ((lane & 15) * 128) + ((lane >> 4) * 16);
    const int bLB = (((lane & 7) + ((lane >> 4) << 3)) * 128) + (((lane >> 3) & 1) * 16);
    const int gRow = lane >> 2;
    const int cPair = (lane & 3) * 2;

    const int bi = blockIdx.x;
    const bf16* Vb  = V  + (size_t)(bi >> 7) * 65536;
    const bf16* T1b = T1 + (size_t)bi * 131072;
    const bf16* Wb  = W  + (size_t)(bi >> 7) * 65536;
    float* Ob = OUT + (size_t)bi * 16384;

    float acc[2][8][4];

    // ---------------- phase A: stage2, two n-halves -------------------------
#pragma unroll
    for (int nh = 0; nh < 2; nh++) {
        const bf16* Bh = T1b + nh * 65536;
        ZERO_ACC(acc);
        __syncthreads();   // pipe region free (prev half / kernel start)

        auto issueA = [&](int c) {
            uint32_t buf = sbP + (c & 1) * 32768;
            load_packed(Vb, c, buf, tid);
            load_packed(Bh, c, buf + 16384, tid);
            CP_COMMIT();
        };
        issueA(0); issueA(1);

#pragma unroll
        for (int c = 0; c < 8; c++) {
            if (c < 7) CP_WAIT1(); else CP_WAIT0();
            __syncthreads();
            uint32_t buf = sbP + (c & 1) * 32768;
            mma_chunk(buf, buf + 16384, acc, aLB, bLB, wm, wn);
            if (c < 6) { __syncthreads(); issueA(c + 2); }
        }

        // write D fragments as bf16 hi|lo into packed SW128 tiles
#pragma unroll
        for (int mi = 0; mi < 2; mi++) {
            int row0 = wm * 32 + mi * 16 + gRow;
#pragma unroll
            for (int f = 0; f < 8; f++) {
                int dcol = nh * 128 + wn * 64 + f * 8 + cPair;
                int ch = dcol >> 5, dc = dcol & 31;
#pragma unroll
                for (int hh = 0; hh < 2; hh++) {
                    int row = row0 + hh * 8;
                    float v0 = acc[mi][f][hh * 2 + 0];
                    float v1 = acc[mi][f][hh * 2 + 1];
                    bf16 h0 = __float2bfloat16(v0);
                    bf16 l0 = __float2bfloat16(v0 - __bfloat162float(h0));
                    bf16 h1 = __float2bfloat16(v1);
                    bf16 l1 = __float2bfloat16(v1 - __bfloat162float(h1));
                    __nv_bfloat162 ph; ph.x = h0; ph.y = h1;
                    __nv_bfloat162 pl; pl.x = l0; pl.y = l1;
                    *(__nv_bfloat162*)(sbp + ch * 16384 + SW128(row * 128 + dc * 2)) = ph;
                    *(__nv_bfloat162*)(sbp + ch * 16384 + SW128(row * 128 + 64 + dc * 2)) = pl;
                }
            }
        }
    }
    __syncthreads();   // D complete, pipe free

    // ---------------- phase B: stage3 from smem ------------------------------
    ZERO_ACC(acc);
    auto issueB = [&](int c) {
        load_packed(Wb, c, sbP + (c & 1) * 16384, tid);
        CP_COMMIT();
    };
    issueB(0); issueB(1);

#pragma unroll
    for (int c = 0; c < 8; c++) {
        if (c < 7) CP_WAIT1(); else CP_WAIT0();
        __syncthreads();
        mma_chunk(sbD + c * 16384, sbP + (c & 1) * 16384, acc, aLB, bLB, wm, wn);
        if (c < 6) { __syncthreads(); issueB(c + 2); }
    }

    // f32 scores out
#pragma unroll
    for (int mi = 0; mi < 2; mi++) {
        int row0 = wm * 32 + mi * 16 + gRow;
#pragma unroll
        for (int f = 0; f < 8; f++) {
            int col = wn * 64 + f * 8 + cPair;
#pragma unroll
            for (int hh = 0; hh < 2; hh++) {
                int row = row0 + hh * 8;
                *(float2*)(Ob + (size_t)row * 128 + col) =
                    make_float2(acc[mi][f][hh * 2 + 0], acc[mi][f][hh * 2 + 1]);
            }
        }
    }
}

// ===========================================================================
// Projection GEMM (SIMT fp32): elu(h @ W + b) -> bf16 hi|lo rows [1024,512]
// ===========================================================================
struct ProjArgs {
    const float* W[7];
    const float* bias[7];
};

__global__ __launch_bounds__(256, 2)
void proj_gemm(ProjArgs pa, const float* __restrict__ h, bf16* __restrict__ outp)
{
    __shared__ float As[16][128];
    __shared__ float Bs[16][128];

    const int br = blockIdx.z;
    const float* A = h;
    const float* B = pa.W[br];
    const float* bias = pa.bias[br];

    const int tid = threadIdx.x;
    const int bm = blockIdx.y * 128;
    const int bn = blockIdx.x * 128;
    const int tx = tid & 15;
    const int ty = tid >> 4;

    float acc[8][8];
#pragma unroll
    for (int i = 0; i < 8; i++)
#pragma unroll
        for (int j = 0; j < 8; j++) acc[i][j] = 0.0f;

    for (int k0 = 0; k0 < 512; k0 += 16) {
#pragma unroll
        for (int i = 0; i < 2; i++) {
            int v = tid + i * 256;
            int r = v >> 2;
            int c4 = (v & 3) << 2;
            float4 a = *(const float4*)(A + (size_t)(bm + r) * 512 + k0 + c4);
            As[c4 + 0][r] = a.x; As[c4 + 1][r] = a.y;
            As[c4 + 2][r] = a.z; As[c4 + 3][r] = a.w;
        }
#pragma unroll
        for (int i = 0; i < 2; i++) {
            int v = tid + i * 256;
            int r = v >> 5;
            int c4 = (v & 31) << 2;
            float4 b = *(const float4*)(B + (size_t)(k0 + r) * 256 + bn + c4);
            *(float4*)&Bs[r][c4] = b;
        }
        __syncthreads();
#pragma unroll
        for (int kk = 0; kk < 16; kk++) {
            float ar[8], brg[8];
            *(float4*)&ar[0] = *(const float4*)&As[kk][ty * 8];
            *(float4*)&ar[4] = *(const float4*)&As[kk][ty * 8 + 4];
            *(float4*)&brg[0] = *(const float4*)&Bs[kk][tx * 8];
            *(float4*)&brg[4] = *(const float4*)&Bs[kk][tx * 8 + 4];
#pragma unroll
            for (int i = 0; i < 8; i++)
#pragma unroll
                for (int j = 0; j < 8; j++)
                    acc[i][j] = fmaf(ar[i], brg[j], acc[i][j]);
        }
        __syncthreads();
    }

    bf16* Co = outp + (size_t)br * (1024 * 512);
#pragma unroll
    for (int i = 0; i < 8; i++) {
        int r = bm + ty * 8 + i;
#pragma unroll
        for (int j = 0; j < 8; j++) {
            int col = bn + tx * 8 + j;
            float v = acc[i][j] + bias[col];
            v = v > 0.f ? v : expm1f(v);
            bf16 hb = __float2bfloat16(v);
            bf16 lb = __float2bfloat16(v - __bfloat162float(hb));
            Co[(size_t)r * 512 + col] = hb;
            Co[(size_t)r * 512 + 256 + col] = lb;
        }
    }
}

// ===========================================================================
// U permute+split: U[a,c,d] f32 -> Up[(d*256+c)][a] hi, [(d*256+c)][256+a] lo
// ===========================================================================
__global__ void uconv(const float* __restrict__ U, bf16* __restrict__ Up)
{
    __shared__ float t[32][33];
    const int c = blockIdx.z;
    const int d0 = blockIdx.x * 32;
    const int a0 = blockIdx.y * 32;
    const int tx = threadIdx.x;
    const int ty = threadIdx.y;

#pragma unroll
    for (int i = 0; i < 32; i += 8)
        t[ty + i][tx] = U[(size_t)(a0 + ty + i) * 65536 + c * 256 + d0 + tx];
    __syncthreads();
#pragma unroll
    for (int i = 0; i < 32; i += 8) {
        int dl = ty + i;
        float v = t[tx][dl];
        bf16 hb = __float2bfloat16(v);
        bf16 lb = __float2bfloat16(v - __bfloat162float(hb));
        size_t rowbase = ((size_t)(d0 + dl) * 256 + c) * 512;
        Up[rowbase + a0 + tx] = hb;
        Up[rowbase + 256 + a0 + tx] = lb;
    }
}

__global__ void build_h(const float* __restrict__ x, const float* __restrict__ sent,
                        float* __restrict__ h)
{
    int idx = blockIdx.x * blockDim.x + threadIdx.x;
    int rowi = idx >> 9;
    int e = idx & 511;
    int t = rowi & 127;
    int b = rowi >> 7;
    h[idx] = (t == 0) ? sent[e] : x[((size_t)(b * 127 + t - 1)) * 512 + e];
}

__global__ void write_mask(const int* __restrict__ mask, float* __restrict__ outm)
{
    int i = blockIdx.x * blockDim.x + threadIdx.x;
    if (i < 1024) {
        int b = i >> 7, t = i & 127;
        outm[i] = (t == 0) ? 1.0f : (float)mask[b * 127 + t - 1];
    }
}

// ===========================================================================
extern "C" void kernel_launch(void* const* d_in, const int* in_sizes, int n_in,
                              void* d_out, int out_size)
{
    (void)in_sizes; (void)n_in; (void)out_size;

    const float* x    = (const float*)d_in[0];
    const int*   mask = (const int*)d_in[2];
    const float* U[3] = { (const float*)d_in[17], (const float*)d_in[18], (const float*)d_in[19] };
    const float* sent = (const float*)d_in[20];
    float* out = (float*)d_out;

    float* h;
    bf16 *projb, *Up, *t1;
    cudaGetSymbolAddress((void**)&h,     g_h);
    cudaGetSymbolAddress((void**)&projb, g_projb);
    cudaGetSymbolAddress((void**)&Up,    g_Up);
    cudaGetSymbolAddress((void**)&t1,    g_t1);

    const int SMEM1 = 2 * 32768 + 1024;                 // 66560
    const int SMEMF = 131072 + 2 * 32768 + 1024;        // 197632
    cudaFuncSetAttribute(stage1_mma,    cudaFuncAttributeMaxDynamicSharedMemorySize, SMEM1);
    cudaFuncSetAttribute(fused_stage23, cudaFuncAttributeMaxDynamicSharedMemorySize, SMEMF);

    build_h<<<2048, 256>>>(x, sent, h);

    const size_t SCORES = (size_t)3 * 16777216;
    write_mask<<<4, 256>>>(mask, out + SCORES);

    ProjArgs pa;
    for (int i = 0; i < 7; i++) {
        pa.W[i]    = (const float*)d_in[3 + 2 * i];
        pa.bias[i] = (const float*)d_in[4 + 2 * i];
    }
    proj_gemm<<<dim3(2, 8, 7), 256>>>(pa, h, projb);

    for (int t = 0; t < 3; t++)
        uconv<<<dim3(8, 8, 256), dim3(32, 8)>>>(U[t], Up + (size_t)t * 65536 * 512);

    const size_t PB = 1024 * 512;
    const int ui[3] = {0, 2, 4};
    const int vi[3] = {1, 3, 6};
    const int wi[3] = {1, 2, 5};

    for (int t = 0; t < 3; t++) {
        stage1_mma<<<dim3(8, 512), 256, SMEM1>>>(
            projb + ui[t] * PB, Up + (size_t)t * 65536 * 512, t1);

        fused_stage23<<<1024, 256, SMEMF>>>(
            projb + vi[t] * PB, t1, projb + wi[t] * PB, out + (size_t)t * 16777216);
    }
}

// round 5
// speedup vs baseline: 2.5446x; 1.0580x over previous
#include <cuda_runtime.h>
#include <cuda_bf16.h>
#include <cstdint>
#include <math.h>

typedef __nv_bfloat16 bf16;

// ===========================================================================
// TriParser via mma.sync (HMMA bf16, f32 acc), split-bf16 (hi/lo) fp32 emu.
//   proj: elu(h@W+b) -> bf16 hi|lo rows [1024, 512]   (7 branches)
//   Up:   U[a,c,d] -> rows r=d*256+c, cols a hi|lo    [65536, 512]
//   stage1: t1[bi][d][c] = u @ Up^T
//   stage2: t2[bi][j][d] = v[b] @ t1[bi]^T
//   stage3: s[bi][j][k]  = t2[bi] @ w[b]^T  (f32 out)
// D = Ah@Bh + Ah@Bl + Al@Bh. All stages share one kernel (occupancy 2/SM).
// ===========================================================================

__device__ float g_h[1024 * 512];                      // 2 MB
__device__ bf16  g_projb[7 * 1024 * 512];              // 7 MB
__device__ bf16  g_Up[3ull * 65536 * 512];             // 192 MB
__device__ bf16  g_t1[1024ull * 256 * 512];            // 268 MB
__device__ bf16  g_t2[1024ull * 128 * 512];            // 134 MB

__device__ __forceinline__ uint32_t smem_u32(const void* p) {
    uint32_t a;
    asm("{ .reg .u64 t; cvta.to.shared.u64 t, %1; cvt.u32.u64 %0, t; }"
        : "=r"(a) : "l"(p));
    return a;
}

#define SW128(o) ((o) ^ (((o) >> 3) & 0x70))

__device__ __forceinline__ void ldm_x4(uint32_t* r, uint32_t addr) {
    asm volatile("ldmatrix.sync.aligned.m8n8.x4.shared.b16 {%0,%1,%2,%3}, [%4];"
                 : "=r"(r[0]), "=r"(r[1]), "=r"(r[2]), "=r"(r[3]) : "r"(addr));
}

__device__ __forceinline__ void mma16816(float* c, const uint32_t* a, const uint32_t* b) {
    asm volatile(
        "mma.sync.aligned.m16n8k16.row.col.f32.bf16.bf16.f32 "
        "{%0,%1,%2,%3}, {%4,%5,%6,%7}, {%8,%9}, {%0,%1,%2,%3};"
        : "+f"(c[0]), "+f"(c[1]), "+f"(c[2]), "+f"(c[3])
        : "r"(a[0]), "r"(a[1]), "r"(a[2]), "r"(a[3]), "r"(b[0]), "r"(b[1]));
}

__device__ __forceinline__ void cpa16(uint32_t dst, const void* src) {
    asm volatile("cp.async.cg.shared.global [%0], [%1], 16;" :: "r"(dst), "l"(src) : "memory");
}
#define CP_COMMIT() asm volatile("cp.async.commit_group;" ::: "memory")
#define CP_WAIT1()  asm volatile("cp.async.wait_group 1;" ::: "memory")
#define CP_WAIT0()  asm volatile("cp.async.wait_group 0;" ::: "memory")

// Packed tile loader: source rows [row, 512] bf16 (hi 0:256 | lo 256:512).
// Chunk c covers K cols [c*32, c*32+32). Tile = 128 rows x 128B (hi|lo), SW128.
__device__ __forceinline__ void load_packed(const bf16* __restrict__ g, int c,
                                            uint32_t dst, int tid) {
#pragma unroll
    for (int i = 0; i < 4; i++) {
        int idx = tid + i * 256;
        int row = idx >> 3, seg = idx & 7;
        int col = (seg < 4) ? c * 32 + seg * 8 : 256 + c * 32 + (seg - 4) * 8;
        cpa16(dst + SW128(row * 128 + seg * 16), g + (size_t)row * 512 + col);
    }
}

// One K-chunk(32) of the 128x128 3-product MMA. Warp tile 32x64 (wm 0-3, wn 0-1).
__device__ __forceinline__ void mma_chunk(uint32_t aBase, uint32_t bBase,
                                          float (&acc)[2][8][4],
                                          int aLB, int bLB, int wm, int wn) {
#pragma unroll
    for (int kk = 0; kk < 2; kk++) {
        uint32_t ah[2][4], al[2][4], bh[4][4], bl[4][4];
#pragma unroll
        for (int mi = 0; mi < 2; mi++) {
            int off = aLB + (wm * 32 + mi * 16) * 128 + kk * 32;
            ldm_x4(ah[mi], aBase + SW128(off));
            ldm_x4(al[mi], aBase + SW128(off + 64));
        }
#pragma unroll
        for (int nj = 0; nj < 4; nj++) {
            int off = bLB + (wn * 64 + nj * 16) * 128 + kk * 32;
            ldm_x4(bh[nj], bBase + SW128(off));
            ldm_x4(bl[nj], bBase + SW128(off + 64));
        }
#pragma unroll
        for (int mi = 0; mi < 2; mi++)
#pragma unroll
            for (int nj = 0; nj < 4; nj++) {
                mma16816(acc[mi][nj * 2],     ah[mi], &bh[nj][0]);
                mma16816(acc[mi][nj * 2 + 1], ah[mi], &bh[nj][2]);
                mma16816(acc[mi][nj * 2],     ah[mi], &bl[nj][0]);
                mma16816(acc[mi][nj * 2 + 1], ah[mi], &bl[nj][2]);
                mma16816(acc[mi][nj * 2],     al[mi], &bh[nj][0]);
                mma16816(acc[mi][nj * 2 + 1], al[mi], &bh[nj][2]);
            }
    }
}

#define ZERO_ACC(acc) \
    { _Pragma("unroll") for (int i = 0; i < 2; i++) \
      _Pragma("unroll") for (int j = 0; j < 8; j++) \
      _Pragma("unroll") for (int k = 0; k < 4; k++) acc[i][j][k] = 0.0f; }

// ===========================================================================
// Generic MMA stage, 256 threads, 2 CTAs/SM.
// D[128,128] = 3-product A[128,256]@B[128,256]^T (hi|lo packed operands).
// EPI=0 bf16 hi|lo out; EPI=1 f32 out. S1MAP: stage1 output column mapping.
// ===========================================================================
template <int EPI, int S1MAP>
__global__ __launch_bounds__(256, 2)
void mma_stage(const bf16* __restrict__ A, const bf16* __restrict__ B,
               void* __restrict__ Cv,
               unsigned long long aBatch, int aShift,
               unsigned long long bBatch, int bShift,
               unsigned long long cBatch, unsigned long long cRowStride)
{
    extern __shared__ char dsm[];
    const uint32_t sraw = smem_u32(dsm);
    const uint32_t sb = (sraw + 1023u) & ~1023u;

    const int tid = threadIdx.x;
    const int lane = tid & 31;
    const int warp = tid >> 5;
    const int wm = warp >> 1, wn = warp & 1;
    const int aLB = ((lane & 15) * 128) + ((lane >> 4) * 16);
    const int bLB = (((lane & 7) + ((lane >> 4) << 3)) * 128) + (((lane >> 3) & 1) * 16);
    const size_t z = blockIdx.z;

    const bf16* Ab = A + (z >> aShift) * (size_t)aBatch + (size_t)blockIdx.x * 65536;
    const bf16* Bb = B + (z >> bShift) * (size_t)bBatch + (size_t)blockIdx.y * 65536;

    float acc[2][8][4];
    ZERO_ACC(acc);

    auto issue = [&](int c) {
        uint32_t buf = sb + (c & 1) * 32768;
        load_packed(Ab, c, buf, tid);
        load_packed(Bb, c, buf + 16384, tid);
        CP_COMMIT();
    };
    issue(0); issue(1);

#pragma unroll
    for (int c = 0; c < 8; c++) {
        if (c < 7) CP_WAIT1(); else CP_WAIT0();
        __syncthreads();
        uint32_t buf = sb + (c & 1) * 32768;
        mma_chunk(buf, buf + 16384, acc, aLB, bLB, wm, wn);
        if (c < 6) { __syncthreads(); issue(c + 2); }
    }

    const int gRow = lane >> 2;
    const int cPair = (lane & 3) * 2;

    if (EPI == 0) {
        bf16* Cb = (bf16*)Cv + z * cBatch;
        const size_t colBase = S1MAP
            ? ((size_t)(blockIdx.y >> 1) * 512 + (size_t)(blockIdx.y & 1) * 128)
            : (size_t)blockIdx.y * 128;
#pragma unroll
        for (int mi = 0; mi < 2; mi++) {
            int rbase = blockIdx.x * 128 + wm * 32 + mi * 16 + gRow;
#pragma unroll
            for (int f = 0; f < 8; f++) {
                int nloc = wn * 64 + f * 8 + cPair;
#pragma unroll
                for (int hh = 0; hh < 2; hh++) {
                    float v0 = acc[mi][f][hh * 2 + 0];
                    float v1 = acc[mi][f][hh * 2 + 1];
                    size_t row = (size_t)(rbase + hh * 8);
                    bf16 h0 = __float2bfloat16(v0);
                    bf16 l0 = __float2bfloat16(v0 - __bfloat162float(h0));
                    bf16 h1 = __float2bfloat16(v1);
                    bf16 l1 = __float2bfloat16(v1 - __bfloat162float(h1));
                    __nv_bfloat162 ph; ph.x = h0; ph.y = h1;
                    __nv_bfloat162 pl; pl.x = l0; pl.y = l1;
                    *(__nv_bfloat162*)(Cb + row * cRowStride + colBase + nloc) = ph;
                    *(__nv_bfloat162*)(Cb + row * cRowStride + colBase + 256 + nloc) = pl;
                }
            }
        }
    } else {
        float* Cb = (float*)Cv + z * cBatch;
#pragma unroll
        for (int mi = 0; mi < 2; mi++) {
            int rbase = blockIdx.x * 128 + wm * 32 + mi * 16 + gRow;
#pragma unroll
            for (int f = 0; f < 8; f++) {
                int col = blockIdx.y * 128 + wn * 64 + f * 8 + cPair;
#pragma unroll
                for (int hh = 0; hh < 2; hh++) {
                    size_t row = (size_t)(rbase + hh * 8);
                    *(float2*)(Cb + row * 128 + col) =
                        make_float2(acc[mi][f][hh * 2 + 0], acc[mi][f][hh * 2 + 1]);
                }
            }
        }
    }
}

// ===========================================================================
// Projection GEMM (SIMT fp32): elu(h @ W + b) -> bf16 hi|lo rows [1024,512]
// ===========================================================================
struct ProjArgs {
    const float* W[7];
    const float* bias[7];
};

__global__ __launch_bounds__(256, 2)
void proj_gemm(ProjArgs pa, const float* __restrict__ h, bf16* __restrict__ outp)
{
    __shared__ float As[16][128];
    __shared__ float Bs[16][128];

    const int br = blockIdx.z;
    const float* A = h;
    const float* B = pa.W[br];
    const float* bias = pa.bias[br];

    const int tid = threadIdx.x;
    const int bm = blockIdx.y * 128;
    const int bn = blockIdx.x * 128;
    const int tx = tid & 15;
    const int ty = tid >> 4;

    float acc[8][8];
#pragma unroll
    for (int i = 0; i < 8; i++)
#pragma unroll
        for (int j = 0; j < 8; j++) acc[i][j] = 0.0f;

    for (int k0 = 0; k0 < 512; k0 += 16) {
#pragma unroll
        for (int i = 0; i < 2; i++) {
            int v = tid + i * 256;
            int r = v >> 2;
            int c4 = (v & 3) << 2;
            float4 a = *(const float4*)(A + (size_t)(bm + r) * 512 + k0 + c4);
            As[c4 + 0][r] = a.x; As[c4 + 1][r] = a.y;
            As[c4 + 2][r] = a.z; As[c4 + 3][r] = a.w;
        }
#pragma unroll
        for (int i = 0; i < 2; i++) {
            int v = tid + i * 256;
            int r = v >> 5;
            int c4 = (v & 31) << 2;
            float4 b = *(const float4*)(B + (size_t)(k0 + r) * 256 + bn + c4);
            *(float4*)&Bs[r][c4] = b;
        }
        __syncthreads();
#pragma unroll
        for (int kk = 0; kk < 16; kk++) {
            float ar[8], brg[8];
            *(float4*)&ar[0] = *(const float4*)&As[kk][ty * 8];
            *(float4*)&ar[4] = *(const float4*)&As[kk][ty * 8 + 4];
            *(float4*)&brg[0] = *(const float4*)&Bs[kk][tx * 8];
            *(float4*)&brg[4] = *(const float4*)&Bs[kk][tx * 8 + 4];
#pragma unroll
            for (int i = 0; i < 8; i++)
#pragma unroll
                for (int j = 0; j < 8; j++)
                    acc[i][j] = fmaf(ar[i], brg[j], acc[i][j]);
        }
        __syncthreads();
    }

    bf16* Co = outp + (size_t)br * (1024 * 512);
#pragma unroll
    for (int i = 0; i < 8; i++) {
        int r = bm + ty * 8 + i;
#pragma unroll
        for (int j = 0; j < 8; j++) {
            int col = bn + tx * 8 + j;
            float v = acc[i][j] + bias[col];
            v = v > 0.f ? v : expm1f(v);
            bf16 hb = __float2bfloat16(v);
            bf16 lb = __float2bfloat16(v - __bfloat162float(hb));
            Co[(size_t)r * 512 + col] = hb;
            Co[(size_t)r * 512 + 256 + col] = lb;
        }
    }
}

// ===========================================================================
// U permute+split: U[a,c,d] f32 -> Up[(d*256+c)][a] hi, [(d*256+c)][256+a] lo
// ===========================================================================
__global__ void uconv(const float* __restrict__ U, bf16* __restrict__ Up)
{
    __shared__ float t[32][33];
    const int c = blockIdx.z;
    const int d0 = blockIdx.x * 32;
    const int a0 = blockIdx.y * 32;
    const int tx = threadIdx.x;
    const int ty = threadIdx.y;

#pragma unroll
    for (int i = 0; i < 32; i += 8)
        t[ty + i][tx] = U[(size_t)(a0 + ty + i) * 65536 + c * 256 + d0 + tx];
    __syncthreads();
#pragma unroll
    for (int i = 0; i < 32; i += 8) {
        int dl = ty + i;
        float v = t[tx][dl];
        bf16 hb = __float2bfloat16(v);
        bf16 lb = __float2bfloat16(v - __bfloat162float(hb));
        size_t rowbase = ((size_t)(d0 + dl) * 256 + c) * 512;
        Up[rowbase + a0 + tx] = hb;
        Up[rowbase + 256 + a0 + tx] = lb;
    }
}

__global__ void build_h(const float* __restrict__ x, const float* __restrict__ sent,
                        float* __restrict__ h)
{
    int idx = blockIdx.x * blockDim.x + threadIdx.x;
    int rowi = idx >> 9;
    int e = idx & 511;
    int t = rowi & 127;
    int b = rowi >> 7;
    h[idx] = (t == 0) ? sent[e] : x[((size_t)(b * 127 + t - 1)) * 512 + e];
}

__global__ void write_mask(const int* __restrict__ mask, float* __restrict__ outm)
{
    int i = blockIdx.x * blockDim.x + threadIdx.x;
    if (i < 1024) {
        int b = i >> 7, t = i & 127;
        outm[i] = (t == 0) ? 1.0f : (float)mask[b * 127 + t - 1];
    }
}

// ===========================================================================
extern "C" void kernel_launch(void* const* d_in, const int* in_sizes, int n_in,
                              void* d_out, int out_size)
{
    (void)in_sizes; (void)n_in; (void)out_size;

    const float* x    = (const float*)d_in[0];
    const int*   mask = (const int*)d_in[2];
    const float* U[3] = { (const float*)d_in[17], (const float*)d_in[18], (const float*)d_in[19] };
    const float* sent = (const float*)d_in[20];
    float* out = (float*)d_out;

    float* h;
    bf16 *projb, *Up, *t1, *t2;
    cudaGetSymbolAddress((void**)&h,     g_h);
    cudaGetSymbolAddress((void**)&projb, g_projb);
    cudaGetSymbolAddress((void**)&Up,    g_Up);
    cudaGetSymbolAddress((void**)&t1,    g_t1);
    cudaGetSymbolAddress((void**)&t2,    g_t2);

    const int SMEM = 2 * 32768 + 1024;   // 66560 -> 2 CTAs/SM
    cudaFuncSetAttribute(mma_stage<0, 1>, cudaFuncAttributeMaxDynamicSharedMemorySize, SMEM);
    cudaFuncSetAttribute(mma_stage<0, 0>, cudaFuncAttributeMaxDynamicSharedMemorySize, SMEM);
    cudaFuncSetAttribute(mma_stage<1, 0>, cudaFuncAttributeMaxDynamicSharedMemorySize, SMEM);

    // launch order: #0 build_h, #1 proj, #2-4 uconv, #5 stage1(t0) <- ncu window
    build_h<<<2048, 256>>>(x, sent, h);

    ProjArgs pa;
    for (int i = 0; i < 7; i++) {
        pa.W[i]    = (const float*)d_in[3 + 2 * i];
        pa.bias[i] = (const float*)d_in[4 + 2 * i];
    }
    proj_gemm<<<dim3(2, 8, 7), 256>>>(pa, h, projb);

    for (int t = 0; t < 3; t++)
        uconv<<<dim3(8, 8, 256), dim3(32, 8)>>>(U[t], Up + (size_t)t * 65536 * 512);

    const size_t PB = 1024 * 512;
    const int ui[3] = {0, 2, 4};
    const int vi[3] = {1, 3, 6};
    const int wi[3] = {1, 2, 5};

    for (int t = 0; t < 3; t++) {
        // stage1: D[1024, 65536] = u @ Up^T ; x fastest -> 8 CTAs share B tile
        mma_stage<0, 1><<<dim3(8, 512, 1), 256, SMEM>>>(
            projb + ui[t] * PB, Up + (size_t)t * 65536 * 512, t1,
            0ULL, 0, 0ULL, 0, 0ULL, 131072ULL);

        // stage2: per bi: t2[bi][j][d] = v[b] @ t1[bi]^T (two 128-d halves)
        mma_stage<0, 0><<<dim3(1, 2, 1024), 256, SMEM>>>(
            projb + vi[t] * PB, t1, t2,
            65536ULL, 7, 131072ULL, 0, 65536ULL, 512ULL);

        // stage3: per bi: s[bi][j][k] = t2[bi] @ w[b]^T (f32 out)
        mma_stage<1, 0><<<dim3(1, 1, 1024), 256, SMEM>>>(
            t2, projb + wi[t] * PB, out + (size_t)t * 16777216,
            65536ULL, 0, 65536ULL, 7, 16384ULL, 128ULL);
    }

    write_mask<<<4, 256>>>(mask, out + (size_t)3 * 16777216);
}